// round 2
// baseline (speedup 1.0000x reference)
#include <cuda_runtime.h>
#include <math.h>

#define NL 50000
#define KN 16
#define TB 16
#define NB (NL/TB)

// persistent scratch (__device__ globals are allowed)
__device__ float g_WmemT4[128*128];
__device__ float g_WqT4  [228*128];
__device__ float g_WextT4[64*968];     // (d, o=h*484+jp)
__device__ float g_WvextT4[484*128];   // (jp, o2=h*64+d)
__device__ float g_WoutT4[256*128];
__device__ float g_bk[128], g_bv[128];
__device__ float g_df  [(size_t)NL*128];
__device__ float g_c   [NL*2];
__device__ float g_rext[(size_t)NL*968];
__device__ float g_zbar[(size_t)NL*968];

__device__ __forceinline__ float dot4(float4 a, float4 b){
    return fmaf(a.x,b.x, fmaf(a.y,b.y, fmaf(a.z,b.z, a.w*b.w)));
}

// ---- K0: transpose/fold weights ----
__global__ void k0_prep(const float* __restrict__ W_mem, const float* __restrict__ b_mem,
                        const float* __restrict__ W_q,   const float* __restrict__ W_kv,
                        const float* __restrict__ b_kv,  const float* __restrict__ W_out)
{
    const int t = blockIdx.x*blockDim.x + threadIdx.x, nt = gridDim.x*blockDim.x;
    for (int e=t; e<128*128; e+=nt){ int j=e>>7,o=e&127;
        g_WmemT4[((j>>2)*128+o)*4+(j&3)] = W_mem[o*128+j]; }
    for (int e=t; e<228*128; e+=nt){ int j=e/128,o=e-j*128;
        g_WqT4[((j>>2)*128+o)*4+(j&3)] = W_q[o*228+j]; }
    for (int e=t; e<256*128; e+=nt){ int j=e>>7,o=e&127;
        g_WoutT4[((j>>2)*128+o)*4+(j&3)] = W_out[o*256+j]; }
    for (int e=t; e<64*968; e+=nt){
        int d=e/968, o=e-d*968, h=(o>=484), jp=o-h*484, i=h*64+d;
        float v;
        if (jp<356) v = W_kv[i*356+jp];
        else { int m=jp-356; float s=0.f;
               for (int l=0;l<128;l++) s=fmaf(W_kv[i*356+l], W_mem[l*128+m], s); v=s; }
        g_WextT4[((d>>2)*968+o)*4+(d&3)] = v;
    }
    for (int e=t; e<484*128; e+=nt){
        int jp=e>>7, o2=e&127, i=128+o2;
        float v;
        if (jp<356) v = W_kv[i*356+jp];
        else { int m=jp-356; float s=0.f;
               for (int l=0;l<128;l++) s=fmaf(W_kv[i*356+l], W_mem[l*128+m], s); v=s; }
        g_WvextT4[((jp>>2)*128+o2)*4+(jp&3)] = v;
    }
    for (int e=t; e<256; e+=nt){
        float s = b_kv[e];
        for (int l=0;l<128;l++) s = fmaf(W_kv[e*356+l], b_mem[l], s);
        if (e<128) g_bk[e]=s; else g_bv[e-128]=s;
    }
}

// ---- K1: df, t_dst, Q, c, rext (16 rows/block) ----
__global__ void __launch_bounds__(128) k1_qdf(
    const float* __restrict__ memory, const float* __restrict__ dst_feat,
    const float* __restrict__ dst_ts, const int* __restrict__ dst_nodes,
    const float* __restrict__ b_mem,  const float* __restrict__ time_w,
    const float* __restrict__ time_b, const float* __restrict__ b_q)
{
    __shared__ float sM[TB][128];
    __shared__ float sX[TB][232];
    __shared__ float sQ[TB][128];
    __shared__ int   sIdx[TB];
    __shared__ float sTs[TB];
    const int tid = threadIdx.x, row0 = blockIdx.x*TB;

    if (tid < TB){ sIdx[tid]=dst_nodes[row0+tid]; sTs[tid]=dst_ts[row0+tid]; }
    __syncthreads();
    for (int e=tid; e<TB*128; e+=128){ int r=e>>7,c=e&127;
        sM[r][c] = __ldg(&memory[(size_t)sIdx[r]*128 + c]); }
    for (int e=tid; e<TB*100; e+=128){ int r=e/100,d=e-r*100;
        sX[r][128+d] = cosf(fmaf(sTs[r], time_w[d], time_b[d])); }
    __syncthreads();

    const int o = tid;
    { // df
        float acc[TB];
        #pragma unroll
        for (int r=0;r<TB;r++) acc[r]=0.f;
        for (int j4=0;j4<32;j4++){
            float4 w = *(const float4*)&g_WmemT4[(j4*128+o)*4];
            #pragma unroll
            for (int r=0;r<TB;r++){
                float4 x = *(const float4*)&sM[r][j4*4];
                acc[r]=fmaf(w.x,x.x,fmaf(w.y,x.y,fmaf(w.z,x.z,fmaf(w.w,x.w,acc[r]))));
            }
        }
        float bm = b_mem[o];
        #pragma unroll
        for (int r=0;r<TB;r++){
            float v = acc[r] + bm + dst_feat[(size_t)(row0+r)*128 + o];
            sX[r][o]=v; g_df[(size_t)(row0+r)*128 + o]=v;
        }
    }
    __syncthreads();
    { // Q
        float acc[TB];
        #pragma unroll
        for (int r=0;r<TB;r++) acc[r]=0.f;
        for (int j4=0;j4<57;j4++){
            float4 w = *(const float4*)&g_WqT4[(j4*128+o)*4];
            #pragma unroll
            for (int r=0;r<TB;r++){
                float4 x = *(const float4*)&sX[r][j4*4];
                acc[r]=fmaf(w.x,x.x,fmaf(w.y,x.y,fmaf(w.z,x.z,fmaf(w.w,x.w,acc[r]))));
            }
        }
        float bq = b_q[o];
        #pragma unroll
        for (int r=0;r<TB;r++) sQ[r][o] = acc[r] + bq;
    }
    __syncthreads();
    if (tid < 2*TB){ // c
        int r=tid>>1, h=tid&1; float s=0.f;
        for (int d=0;d<64;d++) s = fmaf(sQ[r][h*64+d], g_bk[h*64+d], s);
        g_c[(row0+r)*2+h] = s;
    }
    for (int ot=0; ot<8; ot++){ // rext
        int oo = ot*128 + tid;
        if (oo < 968){
            int h = (oo>=484);
            float acc[TB];
            #pragma unroll
            for (int r=0;r<TB;r++) acc[r]=0.f;
            for (int j4=0;j4<16;j4++){
                float4 w = *(const float4*)&g_WextT4[(j4*968+oo)*4];
                #pragma unroll
                for (int r=0;r<TB;r++){
                    float4 x = *(const float4*)&sQ[r][h*64 + j4*4];
                    acc[r]=fmaf(w.x,x.x,fmaf(w.y,x.y,fmaf(w.z,x.z,fmaf(w.w,x.w,acc[r]))));
                }
            }
            #pragma unroll
            for (int r=0;r<TB;r++) g_rext[(size_t)(row0+r)*968 + oo] = acc[r];
        }
    }
}

// ---- K2: logits + leakyReLU + softmax + zbar (1 row/block) ----
__global__ void __launch_bounds__(128) k2_attn(
    const float* __restrict__ memory,  const float* __restrict__ src_feat,
    const float* __restrict__ edge_feat, const float* __restrict__ dst_ts,
    const float* __restrict__ src_ts,  const int* __restrict__ src_nodes,
    const float* __restrict__ time_w,  const float* __restrict__ time_b)
{
    __shared__ float sR[968];
    __shared__ float sFeat[KN][484];   // [src|edge|t|M]
    __shared__ float sLogit[2][KN];
    __shared__ float sAttn[2][KN];
    const int n=blockIdx.x, tid=threadIdx.x, lane=tid&31, w=tid>>5;

    for (int e=tid; e<968; e+=128) sR[e] = g_rext[(size_t)n*968 + e];
    __syncthreads();

    const float dts = dst_ts[n];
    for (int k=w; k<KN; k+=4){
        const size_t eb = ((size_t)n*KN + k)*128;
        const int idx = src_nodes[n*KN + k];
        float4 sv = *(const float4*)&src_feat [eb + lane*4];
        float4 ev = *(const float4*)&edge_feat[eb + lane*4];
        float4 mv = __ldg((const float4*)&memory[(size_t)idx*128 + lane*4]);
        float dt = dts - src_ts[n*KN + k]; dt = dt > 0.f ? dt : 0.f;
        float tv0 = cosf(fmaf(dt, time_w[lane   ], time_b[lane   ]));
        float tv1 = cosf(fmaf(dt, time_w[lane+32], time_b[lane+32]));
        float tv2 = cosf(fmaf(dt, time_w[lane+64], time_b[lane+64]));
        float tv3 = 0.f;
        if (lane<4) tv3 = cosf(fmaf(dt, time_w[lane+96], time_b[lane+96]));

        *(float4*)&sFeat[k][lane*4]       = sv;
        *(float4*)&sFeat[k][128+lane*4]   = ev;
        *(float4*)&sFeat[k][356+lane*4]   = mv;
        sFeat[k][256+lane]=tv0; sFeat[k][288+lane]=tv1; sFeat[k][320+lane]=tv2;
        if (lane<4) sFeat[k][352+lane]=tv3;

        float a0,a1;
        {
            float4 r0=*(const float4*)&sR[lane*4],       r1=*(const float4*)&sR[484+lane*4];
            a0=dot4(r0,sv); a1=dot4(r1,sv);
            r0=*(const float4*)&sR[128+lane*4];          r1=*(const float4*)&sR[484+128+lane*4];
            a0+=dot4(r0,ev); a1+=dot4(r1,ev);
            r0=*(const float4*)&sR[356+lane*4];          r1=*(const float4*)&sR[484+356+lane*4];
            a0+=dot4(r0,mv); a1+=dot4(r1,mv);
        }
        a0 += sR[256+lane]*tv0 + sR[288+lane]*tv1 + sR[320+lane]*tv2;
        a1 += sR[484+256+lane]*tv0 + sR[484+288+lane]*tv1 + sR[484+320+lane]*tv2;
        if (lane<4){ a0 += sR[352+lane]*tv3; a1 += sR[484+352+lane]*tv3; }
        #pragma unroll
        for (int sh=16; sh; sh>>=1){
            a0 += __shfl_xor_sync(0xffffffffu, a0, sh);
            a1 += __shfl_xor_sync(0xffffffffu, a1, sh);
        }
        if (lane==0){ sLogit[0][k]=a0+g_c[n*2]; sLogit[1][k]=a1+g_c[n*2+1]; }
    }
    __syncthreads();
    if (tid < 2){
        const int h=tid; float v[KN], m=-3.4e38f;
        #pragma unroll
        for (int k=0;k<KN;k++){ float x=sLogit[h][k]; x = x>=0.f ? x : 0.2f*x;
                                v[k]=x; m=fmaxf(m,x); }
        float s=0.f;
        #pragma unroll
        for (int k=0;k<KN;k++){ float e=expf(v[k]-m); sAttn[h][k]=e; s+=e; }
        float inv=1.f/s;
        #pragma unroll
        for (int k=0;k<KN;k++) sAttn[h][k]*=inv;
    }
    __syncthreads();
    for (int oo=tid; oo<968; oo+=128){
        const int h=(oo>=484), jp=oo-h*484;
        float acc=0.f;
        #pragma unroll
        for (int k=0;k<KN;k++) acc = fmaf(sAttn[h][k], sFeat[k][jp], acc);
        g_zbar[(size_t)n*968 + oo] = acc;
    }
}

// ---- K3: attn-out + out-proj + ReLU + LayerNorm (16 rows/block) ----
__global__ void __launch_bounds__(128) k3_out(
    const float* __restrict__ b_out, const float* __restrict__ ln_g,
    const float* __restrict__ ln_b,  float* __restrict__ out)
{
    __shared__ float sX[TB][256];
    __shared__ float sV[TB][128];
    const int tid=threadIdx.x, row0=blockIdx.x*TB;

    for (int e=tid; e<TB*128; e+=128)
        sX[e>>7][128+(e&127)] = g_df[(size_t)row0*128 + e];
    __syncthreads();

    const int o = tid;
    { // attn_out[o] = Wvext[:,o] . zbar_h + bv'[o]
        float acc[TB];
        #pragma unroll
        for (int r=0;r<TB;r++) acc[r]=0.f;
        const int h = o>>6;
        const float* zb = &g_zbar[(size_t)row0*968 + (size_t)h*484];
        for (int j4=0;j4<121;j4++){
            float4 w = *(const float4*)&g_WvextT4[(j4*128+o)*4];
            #pragma unroll
            for (int r=0;r<TB;r++){
                float4 x = __ldg((const float4*)&zb[(size_t)r*968 + j4*4]);
                acc[r]=fmaf(w.x,x.x,fmaf(w.y,x.y,fmaf(w.z,x.z,fmaf(w.w,x.w,acc[r]))));
            }
        }
        float bv = g_bv[o];
        #pragma unroll
        for (int r=0;r<TB;r++) sX[r][o] = acc[r] + bv;
    }
    __syncthreads();
    { // relu([attn_out, df] @ W_out^T + b_out)
        float acc[TB];
        #pragma unroll
        for (int r=0;r<TB;r++) acc[r]=0.f;
        for (int j4=0;j4<64;j4++){
            float4 w = *(const float4*)&g_WoutT4[(j4*128+o)*4];
            #pragma unroll
            for (int r=0;r<TB;r++){
                float4 x = *(const float4*)&sX[r][j4*4];
                acc[r]=fmaf(w.x,x.x,fmaf(w.y,x.y,fmaf(w.z,x.z,fmaf(w.w,x.w,acc[r]))));
            }
        }
        float bo = b_out[o];
        #pragma unroll
        for (int r=0;r<TB;r++){ float v=acc[r]+bo; sV[r][o] = v>0.f ? v : 0.f; }
    }
    __syncthreads();
    const int lane=tid&31, w=tid>>5;
    for (int r=w; r<TB; r+=4){
        float4 x = *(const float4*)&sV[r][lane*4];
        float s = x.x+x.y+x.z+x.w;
        #pragma unroll
        for (int sh=16; sh; sh>>=1) s += __shfl_xor_sync(0xffffffffu, s, sh);
        float mu = s*(1.f/128.f);
        float dx=x.x-mu, dy=x.y-mu, dz=x.z-mu, dw=x.w-mu;
        float q = dx*dx+dy*dy+dz*dz+dw*dw;
        #pragma unroll
        for (int sh=16; sh; sh>>=1) q += __shfl_xor_sync(0xffffffffu, q, sh);
        float rs = rsqrtf(q*(1.f/128.f) + 1e-5f);
        float4 g = *(const float4*)&ln_g[lane*4];
        float4 b = *(const float4*)&ln_b[lane*4];
        float4 y;
        y.x = dx*rs*g.x + b.x; y.y = dy*rs*g.y + b.y;
        y.z = dz*rs*g.z + b.z; y.w = dw*rs*g.w + b.w;
        *(float4*)&out[(size_t)(row0+r)*128 + lane*4] = y;
    }
}

extern "C" void kernel_launch(void* const* d_in, const int* in_sizes, int n_in,
                              void* d_out, int out_size)
{
    const float* memory    = (const float*)d_in[0];
    const float* dst_feat  = (const float*)d_in[1];
    const float* src_feat  = (const float*)d_in[2];
    const float* edge_feat = (const float*)d_in[3];
    const float* dst_ts    = (const float*)d_in[4];
    const float* src_ts    = (const float*)d_in[5];
    const int*   dst_nodes = (const int*)d_in[6];
    const int*   src_nodes = (const int*)d_in[7];
    const float* W_mem     = (const float*)d_in[8];
    const float* b_mem     = (const float*)d_in[9];
    const float* time_w    = (const float*)d_in[10];
    const float* time_b    = (const float*)d_in[11];
    const float* W_q       = (const float*)d_in[12];
    const float* b_q       = (const float*)d_in[13];
    const float* W_kv      = (const float*)d_in[14];
    const float* b_kv      = (const float*)d_in[15];
    const float* W_out     = (const float*)d_in[16];
    const float* b_out     = (const float*)d_in[17];
    const float* ln_g      = (const float*)d_in[18];
    const float* ln_b      = (const float*)d_in[19];
    float* out = (float*)d_out;

    k0_prep<<<256, 128>>>(W_mem, b_mem, W_q, W_kv, b_kv, W_out);
    k1_qdf<<<NB, 128>>>(memory, dst_feat, dst_ts, dst_nodes, b_mem, time_w, time_b, b_q);
    k2_attn<<<NL, 128>>>(memory, src_feat, edge_feat, dst_ts, src_ts, src_nodes, time_w, time_b);
    k3_out<<<NB, 128>>>(b_out, ln_g, ln_b, out);
}

// round 3
// speedup vs baseline: 1.0192x; 1.0192x over previous
#include <cuda_runtime.h>
#include <math.h>

#define NL 50000
#define KN 16
#define TB 16
#define NB (NL/TB)

typedef unsigned long long u64;

// ---------------- persistent device scratch ----------------
__device__ float g_Wm2[64*64*4];     // (j2, po): 4 slots = {j=2j2:(o_lo,o_hi), j=2j2+1:(o_lo,o_hi)}
__device__ float g_Wq2[114*64*4];
__device__ float g_Wo2[128*64*4];
__device__ float g_We2[32*484*4];    // (d2, jp): {d=2d2:(h0,h1), d=2d2+1:(h0,h1)}
__device__ float g_Wv2[242*64*4];    // (jp2, d): {jp=2jp2:(h0,h1), jp=2jp2+1:(h0,h1)}
__device__ float2 g_bk2[64];
__device__ float g_bv[128];
__device__ float g_df  [(size_t)NL*128];
__device__ float g_c   [NL*2];
__device__ float g_rext[(size_t)NL*968];   // interleaved pairs (h0,h1) per jp
__device__ float g_zbar[(size_t)NL*968];   // interleaved pairs (h0,h1) per jp

__device__ __forceinline__ void fma2(u64 &d, u64 a, u64 b){
    asm("fma.rn.f32x2 %0, %1, %2, %0;" : "+l"(d) : "l"(a), "l"(b));
}
__device__ __forceinline__ float2 upk(u64 v){
    float lo, hi;
    asm("mov.b64 {%0,%1}, %2;" : "=f"(lo), "=f"(hi) : "l"(v));
    return make_float2(lo, hi);
}

// ---- K0: build packed weights ----
__global__ void k0_prep(const float* __restrict__ W_mem, const float* __restrict__ b_mem,
                        const float* __restrict__ W_q,   const float* __restrict__ W_kv,
                        const float* __restrict__ b_kv,  const float* __restrict__ W_out)
{
    const int t = blockIdx.x*blockDim.x + threadIdx.x, nt = gridDim.x*blockDim.x;
    for (int e=t; e<64*64*4; e+=nt){
        int s=e&3, po=(e>>2)&63, j2=e>>8;
        g_Wm2[e] = W_mem[(po + 64*(s&1))*128 + 2*j2 + (s>>1)];
    }
    for (int e=t; e<114*64*4; e+=nt){
        int s=e&3, po=(e>>2)&63, j2=e>>8;
        g_Wq2[e] = W_q[(po + 64*(s&1))*228 + 2*j2 + (s>>1)];
    }
    for (int e=t; e<128*64*4; e+=nt){
        int s=e&3, po=(e>>2)&63, j2=e>>8;
        g_Wo2[e] = W_out[(po + 64*(s&1))*256 + 2*j2 + (s>>1)];
    }
    for (int e=t; e<32*484*4; e+=nt){
        int s=e&3, r=e>>2, jp=r%484, d2=r/484;
        int d = 2*d2 + (s>>1), h = s&1, i = h*64 + d;
        float v;
        if (jp < 356) v = W_kv[i*356 + jp];
        else { int m=jp-356; float acc=0.f;
               for (int l=0;l<128;l++) acc = fmaf(W_kv[i*356+l], W_mem[l*128+m], acc);
               v = acc; }
        g_We2[e] = v;
    }
    for (int e=t; e<242*64*4; e+=nt){
        int s=e&3, r=e>>2, d=r&63, jp2=r>>6;
        int jp = 2*jp2 + (s>>1), h = s&1, i = 128 + h*64 + d;
        float v;
        if (jp < 356) v = W_kv[i*356 + jp];
        else { int m=jp-356; float acc=0.f;
               for (int l=0;l<128;l++) acc = fmaf(W_kv[i*356+l], W_mem[l*128+m], acc);
               v = acc; }
        g_Wv2[e] = v;
    }
    for (int e=t; e<256; e+=nt){
        float s = b_kv[e];
        for (int l=0;l<128;l++) s = fmaf(W_kv[e*356+l], b_mem[l], s);
        if (e < 128){
            if (e < 64) g_bk2[e].x = s; else g_bk2[e-64].y = s;
        } else g_bv[e-128] = s;
    }
}

// ---- K1: df, t_dst, Q, c, rext ----
__global__ void __launch_bounds__(128) k1_qdf(
    const float* __restrict__ memory, const float* __restrict__ dst_feat,
    const float* __restrict__ dst_ts, const int* __restrict__ dst_nodes,
    const float* __restrict__ b_mem,  const float* __restrict__ time_w,
    const float* __restrict__ time_b, const float* __restrict__ b_q)
{
    __shared__ float2 sXd[TB][228];   // dup pairs [df(128)|t_dst(100)]
    __shared__ float2 sMQ[TB][128];   // first dup(memory), then sQ2 pairs (Q[d],Q[64+d])
    __shared__ int   sIdx[TB];
    __shared__ float sTs[TB];
    const int tid = threadIdx.x, row0 = blockIdx.x*TB;

    if (tid < TB){ sIdx[tid]=dst_nodes[row0+tid]; sTs[tid]=dst_ts[row0+tid]; }
    __syncthreads();
    for (int e=tid; e<TB*128; e+=128){
        int r=e>>7, c=e&127;
        float v = __ldg(&memory[(size_t)sIdx[r]*128 + c]);
        sMQ[r][c] = make_float2(v, v);
    }
    for (int e=tid; e<TB*100; e+=128){
        int r=e/100, d=e-r*100;
        float v = cosf(fmaf(sTs[r], time_w[d], time_b[d]));
        sXd[r][128+d] = make_float2(v, v);
    }
    __syncthreads();

    const int po = tid & 63, rg = tid >> 6;      // 8 rows per thread
    { // df: outputs (po, po+64)
        u64 acc[8];
        #pragma unroll
        for (int r=0;r<8;r++) acc[r]=0ull;
        for (int j2=0;j2<64;j2++){
            ulonglong2 w = *(const ulonglong2*)&g_Wm2[(j2*64+po)*4];
            #pragma unroll
            for (int r=0;r<8;r++){
                ulonglong2 x = *(const ulonglong2*)&sMQ[rg*8+r][2*j2];
                fma2(acc[r], w.x, x.x);
                fma2(acc[r], w.y, x.y);
            }
        }
        float bl = b_mem[po], bh = b_mem[po+64];
        #pragma unroll
        for (int r=0;r<8;r++){
            int row = rg*8+r;
            float2 a = upk(acc[r]);
            float lo = a.x + bl + dst_feat[(size_t)(row0+row)*128 + po];
            float hi = a.y + bh + dst_feat[(size_t)(row0+row)*128 + po + 64];
            sXd[row][po]    = make_float2(lo, lo);
            sXd[row][po+64] = make_float2(hi, hi);
            g_df[(size_t)(row0+row)*128 + po]      = lo;
            g_df[(size_t)(row0+row)*128 + po + 64] = hi;
        }
    }
    __syncthreads();
    { // Q: outputs (po, po+64) -> sQ2 pair is exactly (Q[d], Q[64+d])
        u64 acc[8];
        #pragma unroll
        for (int r=0;r<8;r++) acc[r]=0ull;
        for (int j2=0;j2<114;j2++){
            ulonglong2 w = *(const ulonglong2*)&g_Wq2[(j2*64+po)*4];
            #pragma unroll
            for (int r=0;r<8;r++){
                ulonglong2 x = *(const ulonglong2*)&sXd[rg*8+r][2*j2];
                fma2(acc[r], w.x, x.x);
                fma2(acc[r], w.y, x.y);
            }
        }
        float bl = b_q[po], bh = b_q[po+64];
        #pragma unroll
        for (int r=0;r<8;r++){
            float2 a = upk(acc[r]);
            sMQ[rg*8+r][po] = make_float2(a.x + bl, a.y + bh);
        }
    }
    __syncthreads();
    if (tid < TB){ // c[h] = Q_h . bk_h
        float c0=0.f, c1=0.f;
        for (int d=0;d<64;d++){
            float2 q = sMQ[tid][d], b = g_bk2[d];
            c0 = fmaf(q.x, b.x, c0); c1 = fmaf(q.y, b.y, c1);
        }
        g_c[(row0+tid)*2+0]=c0; g_c[(row0+tid)*2+1]=c1;
    }
    // rext pairs (h0,h1) per jp, all 16 rows per thread
    for (int it=0; it<4; it++){
        int jp = tid + it*128;
        if (jp < 484){
            u64 acc[TB];
            #pragma unroll
            for (int r=0;r<TB;r++) acc[r]=0ull;
            for (int d2=0;d2<32;d2++){
                ulonglong2 w = *(const ulonglong2*)&g_We2[(d2*484+jp)*4];
                #pragma unroll
                for (int r=0;r<TB;r++){
                    ulonglong2 x = *(const ulonglong2*)&sMQ[r][2*d2];
                    fma2(acc[r], w.x, x.x);
                    fma2(acc[r], w.y, x.y);
                }
            }
            #pragma unroll
            for (int r=0;r<TB;r++){
                float2 a = upk(acc[r]);
                *(float2*)&g_rext[(size_t)(row0+r)*968 + jp*2] = a;
            }
        }
    }
}

// ---- K2: logits + leakyReLU + softmax + zbar (1 row/block) ----
__global__ void __launch_bounds__(128) k2_attn(
    const float* __restrict__ memory,  const float* __restrict__ src_feat,
    const float* __restrict__ edge_feat, const float* __restrict__ dst_ts,
    const float* __restrict__ src_ts,  const int* __restrict__ src_nodes,
    const float* __restrict__ time_w,  const float* __restrict__ time_b)
{
    __shared__ float sR[968];          // interleaved (h0,h1) per jp
    __shared__ float sFeat[KN][484];
    __shared__ float sLogit[2][KN];
    __shared__ float sAttn[2][KN];
    const int n=blockIdx.x, tid=threadIdx.x, lane=tid&31, w=tid>>5;

    for (int e=tid; e<968; e+=128) sR[e] = g_rext[(size_t)n*968 + e];
    __syncthreads();

    const float dts = dst_ts[n];
    for (int k=w; k<KN; k+=4){
        const size_t eb = ((size_t)n*KN + k)*128;
        const int idx = src_nodes[n*KN + k];
        float4 sv = *(const float4*)&src_feat [eb + lane*4];
        float4 ev = *(const float4*)&edge_feat[eb + lane*4];
        float4 mv = __ldg((const float4*)&memory[(size_t)idx*128 + lane*4]);
        float dt = dts - src_ts[n*KN + k]; dt = dt > 0.f ? dt : 0.f;
        float tv0 = cosf(fmaf(dt, time_w[lane   ], time_b[lane   ]));
        float tv1 = cosf(fmaf(dt, time_w[lane+32], time_b[lane+32]));
        float tv2 = cosf(fmaf(dt, time_w[lane+64], time_b[lane+64]));
        float tv3 = 0.f;
        if (lane<4) tv3 = cosf(fmaf(dt, time_w[lane+96], time_b[lane+96]));

        *(float4*)&sFeat[k][lane*4]     = sv;
        *(float4*)&sFeat[k][128+lane*4] = ev;
        *(float4*)&sFeat[k][356+lane*4] = mv;
        sFeat[k][256+lane]=tv0; sFeat[k][288+lane]=tv1; sFeat[k][320+lane]=tv2;
        if (lane<4) sFeat[k][352+lane]=tv3;

        float a0=0.f, a1=0.f;
        #pragma unroll
        for (int i=0;i<4;i++){
            int jp = lane*4+i; float f = (&sv.x)[i];
            float2 r2 = *(const float2*)&sR[jp*2];
            a0 = fmaf(r2.x, f, a0); a1 = fmaf(r2.y, f, a1);
        }
        #pragma unroll
        for (int i=0;i<4;i++){
            int jp = 128+lane*4+i; float f = (&ev.x)[i];
            float2 r2 = *(const float2*)&sR[jp*2];
            a0 = fmaf(r2.x, f, a0); a1 = fmaf(r2.y, f, a1);
        }
        #pragma unroll
        for (int i=0;i<4;i++){
            int jp = 356+lane*4+i; float f = (&mv.x)[i];
            float2 r2 = *(const float2*)&sR[jp*2];
            a0 = fmaf(r2.x, f, a0); a1 = fmaf(r2.y, f, a1);
        }
        {
            float2 r2;
            r2 = *(const float2*)&sR[(256+lane)*2]; a0=fmaf(r2.x,tv0,a0); a1=fmaf(r2.y,tv0,a1);
            r2 = *(const float2*)&sR[(288+lane)*2]; a0=fmaf(r2.x,tv1,a0); a1=fmaf(r2.y,tv1,a1);
            r2 = *(const float2*)&sR[(320+lane)*2]; a0=fmaf(r2.x,tv2,a0); a1=fmaf(r2.y,tv2,a1);
            if (lane<4){ r2 = *(const float2*)&sR[(352+lane)*2];
                         a0=fmaf(r2.x,tv3,a0); a1=fmaf(r2.y,tv3,a1); }
        }
        #pragma unroll
        for (int sh=16; sh; sh>>=1){
            a0 += __shfl_xor_sync(0xffffffffu, a0, sh);
            a1 += __shfl_xor_sync(0xffffffffu, a1, sh);
        }
        if (lane==0){ sLogit[0][k]=a0+g_c[n*2]; sLogit[1][k]=a1+g_c[n*2+1]; }
    }
    __syncthreads();
    if (tid < 2){
        const int h=tid; float v[KN], m=-3.4e38f;
        #pragma unroll
        for (int k=0;k<KN;k++){ float x=sLogit[h][k]; x = x>=0.f ? x : 0.2f*x;
                                v[k]=x; m=fmaxf(m,x); }
        float s=0.f;
        #pragma unroll
        for (int k=0;k<KN;k++){ float e=expf(v[k]-m); sAttn[h][k]=e; s+=e; }
        float inv=1.f/s;
        #pragma unroll
        for (int k=0;k<KN;k++) sAttn[h][k]*=inv;
    }
    __syncthreads();
    for (int it=0; it<4; it++){
        int jp = tid + it*128;
        if (jp < 484){
            float z0=0.f, z1=0.f;
            #pragma unroll
            for (int k=0;k<KN;k++){
                float f = sFeat[k][jp];
                z0 = fmaf(sAttn[0][k], f, z0);
                z1 = fmaf(sAttn[1][k], f, z1);
            }
            *(float2*)&g_zbar[(size_t)n*968 + jp*2] = make_float2(z0, z1);
        }
    }
}

// ---- K3: attn-out + out-proj + ReLU + LayerNorm ----
__global__ void __launch_bounds__(128) k3_out(
    const float* __restrict__ b_out, const float* __restrict__ ln_g,
    const float* __restrict__ ln_b,  float* __restrict__ out)
{
    __shared__ float2 sXd[TB][256];   // dup pairs [attn_out(128)|df(128)]
    __shared__ float4 sZ[TB][22];     // zbar chunk: 22 jp2 = 44 jp pairs
    __shared__ float  sV[TB][128];
    const int tid=threadIdx.x, row0=blockIdx.x*TB;
    const int d = tid & 63, rg = tid >> 6;

    for (int e=tid; e<TB*128; e+=128){
        float v = g_df[(size_t)row0*128 + e];
        sXd[e>>7][128+(e&127)] = make_float2(v, v);
    }

    // Wvext: outputs (d:h0, d:h1) = o2 = d and 64+d, over 8 rows each
    u64 acc[8];
    #pragma unroll
    for (int r=0;r<8;r++) acc[r]=0ull;
    const float4* gz4 = (const float4*)g_zbar;
    for (int c=0; c<11; c++){
        __syncthreads();
        for (int e=tid; e<TB*22; e+=128){
            int r=e/22, q=e-r*22;
            sZ[r][q] = __ldg(&gz4[(size_t)(row0+r)*242 + c*22 + q]);
        }
        __syncthreads();
        #pragma unroll 2
        for (int q=0; q<22; q++){
            int jp2 = c*22 + q;
            ulonglong2 w = *(const ulonglong2*)&g_Wv2[(jp2*64+d)*4];
            #pragma unroll
            for (int r=0;r<8;r++){
                ulonglong2 x = *(const ulonglong2*)&sZ[rg*8+r][q];
                fma2(acc[r], w.x, x.x);
                fma2(acc[r], w.y, x.y);
            }
        }
    }
    {
        float bl = g_bv[d], bh = g_bv[64+d];
        #pragma unroll
        for (int r=0;r<8;r++){
            int row = rg*8+r;
            float2 a = upk(acc[r]);
            float lo = a.x + bl, hi = a.y + bh;
            sXd[row][d]    = make_float2(lo, lo);
            sXd[row][64+d] = make_float2(hi, hi);
        }
    }
    __syncthreads();
    { // relu([attn_out, df] @ W_out^T + b_out), outputs (d, d+64)
        u64 acc2[8];
        #pragma unroll
        for (int r=0;r<8;r++) acc2[r]=0ull;
        for (int j2=0;j2<128;j2++){
            ulonglong2 w = *(const ulonglong2*)&g_Wo2[(j2*64+d)*4];
            #pragma unroll
            for (int r=0;r<8;r++){
                ulonglong2 x = *(const ulonglong2*)&sXd[rg*8+r][2*j2];
                fma2(acc2[r], w.x, x.x);
                fma2(acc2[r], w.y, x.y);
            }
        }
        float bl = b_out[d], bh = b_out[d+64];
        #pragma unroll
        for (int r=0;r<8;r++){
            int row = rg*8+r;
            float2 a = upk(acc2[r]);
            float lo = a.x + bl, hi = a.y + bh;
            sV[row][d]    = lo > 0.f ? lo : 0.f;
            sV[row][d+64] = hi > 0.f ? hi : 0.f;
        }
    }
    __syncthreads();
    const int lane=tid&31, w=tid>>5;
    for (int r=w; r<TB; r+=4){
        float4 x = *(const float4*)&sV[r][lane*4];
        float s = x.x+x.y+x.z+x.w;
        #pragma unroll
        for (int sh=16; sh; sh>>=1) s += __shfl_xor_sync(0xffffffffu, s, sh);
        float mu = s*(1.f/128.f);
        float dx=x.x-mu, dy=x.y-mu, dz=x.z-mu, dw=x.w-mu;
        float q = dx*dx+dy*dy+dz*dz+dw*dw;
        #pragma unroll
        for (int sh=16; sh; sh>>=1) q += __shfl_xor_sync(0xffffffffu, q, sh);
        float rs = rsqrtf(q*(1.f/128.f) + 1e-5f);
        float4 g = *(const float4*)&ln_g[lane*4];
        float4 b = *(const float4*)&ln_b[lane*4];
        float4 y;
        y.x = dx*rs*g.x + b.x; y.y = dy*rs*g.y + b.y;
        y.z = dz*rs*g.z + b.z; y.w = dw*rs*g.w + b.w;
        *(float4*)&out[(size_t)(row0+r)*128 + lane*4] = y;
    }
}

extern "C" void kernel_launch(void* const* d_in, const int* in_sizes, int n_in,
                              void* d_out, int out_size)
{
    const float* memory    = (const float*)d_in[0];
    const float* dst_feat  = (const float*)d_in[1];
    const float* src_feat  = (const float*)d_in[2];
    const float* edge_feat = (const float*)d_in[3];
    const float* dst_ts    = (const float*)d_in[4];
    const float* src_ts    = (const float*)d_in[5];
    const int*   dst_nodes = (const int*)d_in[6];
    const int*   src_nodes = (const int*)d_in[7];
    const float* W_mem     = (const float*)d_in[8];
    const float* b_mem     = (const float*)d_in[9];
    const float* time_w    = (const float*)d_in[10];
    const float* time_b    = (const float*)d_in[11];
    const float* W_q       = (const float*)d_in[12];
    const float* b_q       = (const float*)d_in[13];
    const float* W_kv      = (const float*)d_in[14];
    const float* b_kv      = (const float*)d_in[15];
    const float* W_out     = (const float*)d_in[16];
    const float* b_out     = (const float*)d_in[17];
    const float* ln_g      = (const float*)d_in[18];
    const float* ln_b      = (const float*)d_in[19];
    float* out = (float*)d_out;

    k0_prep<<<256, 128>>>(W_mem, b_mem, W_q, W_kv, b_kv, W_out);
    k1_qdf<<<NB, 128>>>(memory, dst_feat, dst_ts, dst_nodes, b_mem, time_w, time_b, b_q);
    k2_attn<<<NL, 128>>>(memory, src_feat, edge_feat, dst_ts, src_ts, src_nodes, time_w, time_b);
    k3_out<<<NB, 128>>>(b_out, ln_g, ln_b, out);
}